// round 1
// baseline (speedup 1.0000x reference)
#include <cuda_runtime.h>
#include <cstdint>

#define SQ   2048
#define EDIM 1024
#define FDIM 4096
#define NH   8
#define HD   128
#define NL   4
#define VOC  32000

// Scratch (static device globals are allowed; runtime allocation is not)
__device__ float g_h [SQ * EDIM];
__device__ float g_hf[SQ * FDIM];
__device__ float g_q [SQ * NH * HD];
__device__ float g_k [SQ * NH * HD];
__device__ float g_v [SQ * NH * HD];
__device__ float g_o [SQ * NH * HD];

// ---------------------------------------------------------------------------
// Embedding gather: h[s, :] = embedding[x[s], :]
// ---------------------------------------------------------------------------
__global__ void embed_kernel(const int* __restrict__ x,
                             const float* __restrict__ emb,
                             float* __restrict__ h) {
    int s = blockIdx.x;
    int tok = x[s];
    const float4* src = (const float4*)(emb + (size_t)tok * EDIM);
    float4* dst = (float4*)(h + (size_t)s * EDIM);
    for (int i = threadIdx.x; i < EDIM / 4; i += blockDim.x) dst[i] = src[i];
}

// ---------------------------------------------------------------------------
// Tiled SGEMM: C[M,N] = op(A[M,K] * B)   (row-major everywhere)
//   BT=false: B is [K,N] row-major
//   BT=true : B is [N,K] row-major (i.e. C = A * B^T)
//   RELU: fuse max(0, .) into epilogue
// 128x128 block tile, K-tile 8, 256 threads, 8x8 per thread.
// All of M, N assumed multiples of 128; K multiple of 8.
// ---------------------------------------------------------------------------
template <bool RELU, bool BT>
__global__ __launch_bounds__(256)
void sgemm_kernel(const float* __restrict__ A, const float* __restrict__ B,
                  float* __restrict__ C, int M, int N, int K) {
    __shared__ float As[8][128];
    __shared__ float Bs[8][128];

    int tid = threadIdx.x;
    int m0 = blockIdx.y * 128;
    int n0 = blockIdx.x * 128;
    int ty = tid >> 4;        // 0..15
    int tx = tid & 15;        // 0..15

    float acc[8][8];
#pragma unroll
    for (int i = 0; i < 8; i++)
#pragma unroll
        for (int j = 0; j < 8; j++) acc[i][j] = 0.f;

    for (int k0 = 0; k0 < K; k0 += 8) {
        // A tile: 128 rows x 8 k, stored transposed As[k][m]
        {
            int r  = tid >> 1;
            int kc = (tid & 1) * 4;
            float4 a = *(const float4*)(A + (size_t)(m0 + r) * K + k0 + kc);
            As[kc + 0][r] = a.x; As[kc + 1][r] = a.y;
            As[kc + 2][r] = a.z; As[kc + 3][r] = a.w;
        }
        if (!BT) {
            // B tile: 8 k-rows x 128 n
            int r  = tid >> 5;            // 0..7
            int nc = (tid & 31) * 4;      // 0..124
            float4 b = *(const float4*)(B + (size_t)(k0 + r) * N + n0 + nc);
            *(float4*)&Bs[r][nc] = b;
        } else {
            // B^T tile: read 128 n-rows, 4 k each, store transposed Bs[k][n]
            int n  = tid >> 1;
            int kc = (tid & 1) * 4;
            float4 b = *(const float4*)(B + (size_t)(n0 + n) * K + k0 + kc);
            Bs[kc + 0][n] = b.x; Bs[kc + 1][n] = b.y;
            Bs[kc + 2][n] = b.z; Bs[kc + 3][n] = b.w;
        }
        __syncthreads();

#pragma unroll
        for (int kk = 0; kk < 8; kk++) {
            float a[8], b[8];
            *(float4*)&a[0] = *(const float4*)&As[kk][ty * 8];
            *(float4*)&a[4] = *(const float4*)&As[kk][ty * 8 + 4];
            *(float4*)&b[0] = *(const float4*)&Bs[kk][tx * 8];
            *(float4*)&b[4] = *(const float4*)&Bs[kk][tx * 8 + 4];
#pragma unroll
            for (int i = 0; i < 8; i++)
#pragma unroll
                for (int j = 0; j < 8; j++) acc[i][j] += a[i] * b[j];
        }
        __syncthreads();
    }

#pragma unroll
    for (int i = 0; i < 8; i++) {
        int m = m0 + ty * 8 + i;
#pragma unroll
        for (int j = 0; j < 8; j += 4) {
            float4 o;
            o.x = acc[i][j + 0]; o.y = acc[i][j + 1];
            o.z = acc[i][j + 2]; o.w = acc[i][j + 3];
            if (RELU) {
                o.x = fmaxf(o.x, 0.f); o.y = fmaxf(o.y, 0.f);
                o.z = fmaxf(o.z, 0.f); o.w = fmaxf(o.w, 0.f);
            }
            *(float4*)(C + (size_t)m * N + n0 + tx * 8 + j) = o;
        }
    }
}

// ---------------------------------------------------------------------------
// Causal attention, one (64-query block, head) per CTA. Flash-style online
// softmax. NOTE: reference uses UNSCALED scores (no 1/sqrt(D)).
// Layout of Q/K/V/O: [S, NH*HD] row-major, head h occupies cols h*HD..h*HD+127.
// Thread mapping (256 threads): r = tid/4 (query row 0..63), g = tid%4.
//   scores: thread computes keys [g*16, g*16+16)
//   output: thread accumulates dims [g*32, g*32+32)
// ---------------------------------------------------------------------------
#define QROW_PITCH 132   // 128 + 4 pad (bank-conflict break)
#define P_PITCH    68
#define ATTN_SMEM  ((3 * 64 * QROW_PITCH + 64 * P_PITCH) * 4)

__global__ __launch_bounds__(256)
void attn_kernel(const float* __restrict__ Q, const float* __restrict__ K,
                 const float* __restrict__ Vv, float* __restrict__ O) {
    extern __shared__ float sm[];
    float* q_s = sm;
    float* k_s = q_s + 64 * QROW_PITCH;
    float* v_s = k_s + 64 * QROW_PITCH;
    float* p_s = v_s + 64 * QROW_PITCH;

    int tid  = threadIdx.x;
    int qb   = blockIdx.x;       // 0..31
    int head = blockIdx.y;       // 0..7
    int r = tid >> 2;            // query row within block
    int g = tid & 3;
    int d0 = g * 32;
    int j0 = g * 16;

    // load Q tile
    for (int i = tid; i < 64 * 32; i += 256) {
        int row = i >> 5, c4 = (i & 31) * 4;
        *(float4*)&q_s[row * QROW_PITCH + c4] =
            *(const float4*)(Q + (size_t)(qb * 64 + row) * (NH * HD) + head * HD + c4);
    }

    float acc[32];
#pragma unroll
    for (int d = 0; d < 32; d++) acc[d] = 0.f;
    float m_run = -1e30f, l_run = 0.f;

    __syncthreads();

    for (int kt = 0; kt <= qb; kt++) {
        // load K,V tiles
        for (int i = tid; i < 64 * 32; i += 256) {
            int row = i >> 5, c4 = (i & 31) * 4;
            size_t base = (size_t)(kt * 64 + row) * (NH * HD) + head * HD + c4;
            *(float4*)&k_s[row * QROW_PITCH + c4] = *(const float4*)(K + base);
            *(float4*)&v_s[row * QROW_PITCH + c4] = *(const float4*)(Vv + base);
        }
        __syncthreads();

        // scores for this thread's 16 keys (full 128-dim dot, UNscaled)
        float sc[16];
        const float* qr = &q_s[r * QROW_PITCH];
#pragma unroll 2
        for (int j = 0; j < 16; j++) {
            const float* kr = &k_s[(j0 + j) * QROW_PITCH];
            float s = 0.f;
#pragma unroll 16
            for (int d = 0; d < 128; d++) s += qr[d] * kr[d];
            sc[j] = s;
        }
        if (kt == qb) {
            int qg = qb * 64 + r;
#pragma unroll
            for (int j = 0; j < 16; j++)
                if (kt * 64 + j0 + j > qg) sc[j] = -1e30f;
        }

        // row max across the 4-thread group
        float mt = sc[0];
#pragma unroll
        for (int j = 1; j < 16; j++) mt = fmaxf(mt, sc[j]);
        mt = fmaxf(mt, __shfl_xor_sync(0xffffffffu, mt, 1));
        mt = fmaxf(mt, __shfl_xor_sync(0xffffffffu, mt, 2));
        float m_new = fmaxf(m_run, mt);
        float corr  = __expf(m_run - m_new);

        float ps = 0.f;
#pragma unroll
        for (int j = 0; j < 16; j++) {
            float p = __expf(sc[j] - m_new);
            ps += p;
            p_s[r * P_PITCH + j0 + j] = p;
        }
        ps += __shfl_xor_sync(0xffffffffu, ps, 1);
        ps += __shfl_xor_sync(0xffffffffu, ps, 2);
        l_run = l_run * corr + ps;
        m_run = m_new;
#pragma unroll
        for (int d = 0; d < 32; d++) acc[d] *= corr;
        __syncthreads();

        // acc += P @ V  (this thread: its 32 dims, all 64 keys)
#pragma unroll 1
        for (int j = 0; j < 64; j++) {
            float p = p_s[r * P_PITCH + j];
            const float* vr = &v_s[j * QROW_PITCH + d0];
#pragma unroll
            for (int d = 0; d < 32; d++) acc[d] += p * vr[d];
        }
        __syncthreads();
    }

    float inv = 1.f / l_run;
#pragma unroll
    for (int d = 0; d < 32; d += 4) {
        float4 o;
        o.x = acc[d + 0] * inv; o.y = acc[d + 1] * inv;
        o.z = acc[d + 2] * inv; o.w = acc[d + 3] * inv;
        *(float4*)(O + (size_t)(qb * 64 + r) * (NH * HD) + head * HD + d0 + d) = o;
    }
}

// ---------------------------------------------------------------------------
extern "C" void kernel_launch(void* const* d_in, const int* in_sizes, int n_in,
                              void* d_out, int out_size) {
    const int*   x   = (const int*)d_in[0];
    const float* emb = (const float*)d_in[1];
    const float* ffw = (const float*)d_in[2];   // [L,E,F]
    const float* qw  = (const float*)d_in[3];   // [L,F,H,D]
    const float* kw  = (const float*)d_in[4];
    const float* vw  = (const float*)d_in[5];
    const float* ow  = (const float*)d_in[6];   // [L,H,D,E]
    float* out = (float*)d_out;

    float *h, *hf, *q, *k, *v, *o;
    cudaGetSymbolAddress((void**)&h,  g_h);
    cudaGetSymbolAddress((void**)&hf, g_hf);
    cudaGetSymbolAddress((void**)&q,  g_q);
    cudaGetSymbolAddress((void**)&k,  g_k);
    cudaGetSymbolAddress((void**)&v,  g_v);
    cudaGetSymbolAddress((void**)&o,  g_o);

    cudaFuncSetAttribute(attn_kernel,
                         cudaFuncAttributeMaxDynamicSharedMemorySize, ATTN_SMEM);

    embed_kernel<<<SQ, 256>>>(x, emb, h);

    for (int i = 0; i < NL; i++) {
        const float* ffw_i = ffw + (size_t)i * EDIM * FDIM;
        const float* qw_i  = qw  + (size_t)i * FDIM * NH * HD;
        const float* kw_i  = kw  + (size_t)i * FDIM * NH * HD;
        const float* vw_i  = vw  + (size_t)i * FDIM * NH * HD;
        const float* ow_i  = ow  + (size_t)i * NH * HD * EDIM;

        // hf = relu(h @ ff_w)   [2048,1024]x[1024,4096]
        sgemm_kernel<true, false><<<dim3(FDIM / 128, SQ / 128), 256>>>(
            h, ffw_i, hf, SQ, FDIM, EDIM);

        // q,k,v = hf @ {q,k,v}_w   [2048,4096]x[4096,1024]
        sgemm_kernel<false, false><<<dim3(NH * HD / 128, SQ / 128), 256>>>(
            hf, qw_i, q, SQ, NH * HD, FDIM);
        sgemm_kernel<false, false><<<dim3(NH * HD / 128, SQ / 128), 256>>>(
            hf, kw_i, k, SQ, NH * HD, FDIM);
        sgemm_kernel<false, false><<<dim3(NH * HD / 128, SQ / 128), 256>>>(
            hf, vw_i, v, SQ, NH * HD, FDIM);

        // causal attention
        attn_kernel<<<dim3(SQ / 64, NH), 256, ATTN_SMEM>>>(q, k, v, o);

        // h = o @ o_w   [2048,1024]x[1024,1024]
        sgemm_kernel<false, false><<<dim3(EDIM / 128, SQ / 128), 256>>>(
            o, ow_i, h, SQ, EDIM, NH * HD);
    }

    // logits = h @ embedding^T   [2048,1024]x[32000,1024]^T
    sgemm_kernel<false, true><<<dim3(VOC / 128, SQ / 128), 256>>>(
        h, emb, out, SQ, VOC, EDIM);
}

// round 2
// speedup vs baseline: 2.6368x; 2.6368x over previous
#include <cuda_runtime.h>
#include <cstdint>

#define SQ   2048
#define EDIM 1024
#define FDIM 4096
#define NH   8
#define HD   128
#define NL   4
#define VOC  32000

__device__ float g_h [SQ * EDIM];
__device__ float g_hf[SQ * FDIM];
__device__ float g_q [SQ * NH * HD];
__device__ float g_k [SQ * NH * HD];
__device__ float g_v [SQ * NH * HD];
__device__ float g_o [SQ * NH * HD];

// ---------------------------------------------------------------------------
__global__ void embed_kernel(const int* __restrict__ x,
                             const float* __restrict__ emb,
                             float* __restrict__ h) {
    int s = blockIdx.x;
    int tok = x[s];
    const float4* src = (const float4*)(emb + (size_t)tok * EDIM);
    float4* dst = (float4*)(h + (size_t)s * EDIM);
    for (int i = threadIdx.x; i < EDIM / 4; i += blockDim.x) dst[i] = src[i];
}

// ---------------------------------------------------------------------------
// helpers
// ---------------------------------------------------------------------------
__device__ __forceinline__ uint32_t smem_u32(const void* p) {
    return (uint32_t)__cvta_generic_to_shared(p);
}
__device__ __forceinline__ void cp_async16(uint32_t dst, const void* src) {
    asm volatile("cp.async.cg.shared.global [%0], [%1], 16;\n" :: "r"(dst), "l"(src));
}
__device__ __forceinline__ void cp_commit() {
    asm volatile("cp.async.commit_group;\n");
}
template <int N>
__device__ __forceinline__ void cp_wait() {
    asm volatile("cp.async.wait_group %0;\n" :: "n"(N));
}
__device__ __forceinline__ uint32_t tf32_rna(float x) {
    uint32_t u;
    asm("cvt.rna.tf32.f32 %0, %1;\n" : "=r"(u) : "f"(x));
    return u;
}
__device__ __forceinline__ void mma_tf32(float* c, const uint32_t a[4], const uint32_t b[2]) {
    asm volatile(
        "mma.sync.aligned.m16n8k8.row.col.f32.tf32.tf32.f32 "
        "{%0,%1,%2,%3}, {%4,%5,%6,%7}, {%8,%9}, {%0,%1,%2,%3};\n"
        : "+f"(c[0]), "+f"(c[1]), "+f"(c[2]), "+f"(c[3])
        : "r"(a[0]), "r"(a[1]), "r"(a[2]), "r"(a[3]), "r"(b[0]), "r"(b[1]));
}

// ---------------------------------------------------------------------------
// 3xTF32 GEMM: C[M,N] = op(A[M,K] @ B), fp32-accurate via hi/lo split.
//   BT=false: B is [K,N];  BT=true: B is [N,K]  (C = A @ B^T)
// CTA: 128x128 tile, BK=16, 256 threads = 8 warps (2x4), warp tile 64x32,
// 3-stage cp.async pipeline, raw fp32 in smem, split at fragment load.
// M%128==0, N%128==0, K%16==0 assumed.
// ---------------------------------------------------------------------------
#define APITCH 20          // 16 + 4 pad (floats)
#define BPITCH_N 136       // 128 + 8 pad
#define ASTG (128 * APITCH)
#define GSTAGES 3

template <bool RELU, bool BT>
__device__ __forceinline__ void gemm3t_body(const float* __restrict__ A,
                                            const float* __restrict__ B,
                                            float* __restrict__ C,
                                            int M, int N, int K,
                                            int m0, int n0) {
    constexpr int BSTG = BT ? 128 * APITCH : 16 * BPITCH_N;
    extern __shared__ float sm[];
    float* As = sm;                       // [GSTAGES][ASTG]
    float* Bs = sm + GSTAGES * ASTG;      // [GSTAGES][BSTG]

    int tid  = threadIdx.x;
    int lane = tid & 31;
    int warp = tid >> 5;
    int wr = warp >> 2;                   // 0..1
    int wc = warp & 3;                    // 0..3
    int lq = lane >> 2;                   // 0..7
    int lr = lane & 3;                    // 0..3

    // cp.async addressing
    int ar = tid >> 2;                    // A row 0..63 (and +64)
    int aq = tid & 3;                     // k-quad
    const float* aSrc = A + (size_t)(m0 + ar) * K + aq * 4;
    uint32_t aDst = smem_u32(As) + (uint32_t)(ar * APITCH + aq * 4) * 4u;

    const float* bSrc;
    uint32_t bDst;
    if (BT) {
        int br = tid >> 2, bq = tid & 3;
        bSrc = B + (size_t)(n0 + br) * K + bq * 4;
        bDst = smem_u32(Bs) + (uint32_t)(br * APITCH + bq * 4) * 4u;
    } else {
        int br = tid >> 5, bq = tid & 31;
        bSrc = B + (size_t)br * N + n0 + bq * 4;
        bDst = smem_u32(Bs) + (uint32_t)(br * BPITCH_N + bq * 4) * 4u;
    }

    auto issue = [&](int s, int k0) {
        uint32_t ad = aDst + (uint32_t)(s * ASTG) * 4u;
        cp_async16(ad, aSrc + k0);
        cp_async16(ad + 64u * APITCH * 4u, aSrc + (size_t)64 * K + k0);
        uint32_t bd = bDst + (uint32_t)(s * BSTG) * 4u;
        if (BT) {
            cp_async16(bd, bSrc + k0);
            cp_async16(bd + 64u * APITCH * 4u, bSrc + (size_t)64 * K + k0);
        } else {
            cp_async16(bd, bSrc + (size_t)k0 * N);
            cp_async16(bd + 8u * BPITCH_N * 4u, bSrc + (size_t)(k0 + 8) * N);
        }
    };

    float acc[4][4][4];
#pragma unroll
    for (int i = 0; i < 4; i++)
#pragma unroll
        for (int j = 0; j < 4; j++)
#pragma unroll
            for (int q = 0; q < 4; q++) acc[i][j][q] = 0.f;

    int KT = K >> 4;
    issue(0, 0); cp_commit();
    issue(1, 16); cp_commit();

    for (int kt = 0; kt < KT; kt++) {
        cp_wait<1>();
        __syncthreads();
        int nk = kt + 2;
        if (nk < KT) issue(nk % GSTAGES, nk * 16);
        cp_commit();

        const float* as = As + (kt % GSTAGES) * ASTG;
        const float* bs = Bs + (kt % GSTAGES) * BSTG;

#pragma unroll
        for (int ks = 0; ks < 2; ks++) {
            uint32_t bh[4][2], bl[4][2];
#pragma unroll
            for (int nt = 0; nt < 4; nt++) {
                float r0, r1;
                if (BT) {
                    const float* bp = bs + (wc * 32 + nt * 8 + lq) * APITCH + ks * 8 + lr;
                    r0 = bp[0]; r1 = bp[4];
                } else {
                    const float* bp = bs + (ks * 8 + lr) * BPITCH_N + wc * 32 + nt * 8 + lq;
                    r0 = bp[0]; r1 = bp[4 * BPITCH_N];
                }
                bh[nt][0] = tf32_rna(r0);
                bh[nt][1] = tf32_rna(r1);
                bl[nt][0] = tf32_rna(r0 - __uint_as_float(bh[nt][0]));
                bl[nt][1] = tf32_rna(r1 - __uint_as_float(bh[nt][1]));
            }
#pragma unroll
            for (int mt = 0; mt < 4; mt++) {
                const float* ap = as + (wr * 64 + mt * 16 + lq) * APITCH + ks * 8 + lr;
                float r0 = ap[0], r1 = ap[8 * APITCH], r2 = ap[4], r3 = ap[8 * APITCH + 4];
                uint32_t ah[4], al[4];
                ah[0] = tf32_rna(r0); ah[1] = tf32_rna(r1);
                ah[2] = tf32_rna(r2); ah[3] = tf32_rna(r3);
                al[0] = tf32_rna(r0 - __uint_as_float(ah[0]));
                al[1] = tf32_rna(r1 - __uint_as_float(ah[1]));
                al[2] = tf32_rna(r2 - __uint_as_float(ah[2]));
                al[3] = tf32_rna(r3 - __uint_as_float(ah[3]));
#pragma unroll
                for (int nt = 0; nt < 4; nt++) {
                    mma_tf32(acc[mt][nt], ah, bh[nt]);
                    mma_tf32(acc[mt][nt], ah, bl[nt]);
                    mma_tf32(acc[mt][nt], al, bh[nt]);
                }
            }
        }
        __syncthreads();
    }

    // epilogue
#pragma unroll
    for (int mt = 0; mt < 4; mt++) {
        int r = m0 + wr * 64 + mt * 16 + lq;
#pragma unroll
        for (int nt = 0; nt < 4; nt++) {
            int c = n0 + wc * 32 + nt * 8 + lr * 2;
            float2 v0 = make_float2(acc[mt][nt][0], acc[mt][nt][1]);
            float2 v1 = make_float2(acc[mt][nt][2], acc[mt][nt][3]);
            if (RELU) {
                v0.x = fmaxf(v0.x, 0.f); v0.y = fmaxf(v0.y, 0.f);
                v1.x = fmaxf(v1.x, 0.f); v1.y = fmaxf(v1.y, 0.f);
            }
            *(float2*)(C + (size_t)r * N + c) = v0;
            *(float2*)(C + (size_t)(r + 8) * N + c) = v1;
        }
    }
}

template <bool RELU, bool BT>
__global__ __launch_bounds__(256)
void gemm3t_kernel(const float* __restrict__ A, const float* __restrict__ B,
                   float* __restrict__ C, int M, int N, int K) {
    gemm3t_body<RELU, BT>(A, B, C, M, N, K, blockIdx.y * 128, blockIdx.x * 128);
}

// fused q/k/v: blockIdx.z selects weight + output
__global__ __launch_bounds__(256)
void gemm3t_qkv_kernel(const float* __restrict__ A,
                       const float* __restrict__ B0, const float* __restrict__ B1,
                       const float* __restrict__ B2,
                       float* __restrict__ C0, float* __restrict__ C1,
                       float* __restrict__ C2, int M, int N, int K) {
    const float* B = (blockIdx.z == 0) ? B0 : (blockIdx.z == 1) ? B1 : B2;
    float* C = (blockIdx.z == 0) ? C0 : (blockIdx.z == 1) ? C1 : C2;
    gemm3t_body<false, false>(A, B, C, M, N, K, blockIdx.y * 128, blockIdx.x * 128);
}

// ---------------------------------------------------------------------------
// Causal attention, one (64-query block, head) per CTA; conflict-free lane
// interleave: thread (r = tid/4, g = tid%4):
//   scores: keys j = g + 4*jj (jj=0..15)
//   output: dims  d = g*4 + 16*cc + i (cc=0..7, i=0..3)
// ---------------------------------------------------------------------------
#define QROW_PITCH 132
#define P_PITCH    68
#define ATTN_SMEM  ((3 * 64 * QROW_PITCH + 64 * P_PITCH) * 4)

__global__ __launch_bounds__(256)
void attn_kernel(const float* __restrict__ Q, const float* __restrict__ K,
                 const float* __restrict__ Vv, float* __restrict__ O) {
    extern __shared__ float sm[];
    float* q_s = sm;
    float* k_s = q_s + 64 * QROW_PITCH;
    float* v_s = k_s + 64 * QROW_PITCH;
    float* p_s = v_s + 64 * QROW_PITCH;

    int tid  = threadIdx.x;
    int qb   = blockIdx.x;
    int head = blockIdx.y;
    int r = tid >> 2;
    int g = tid & 3;

    for (int i = tid; i < 64 * 32; i += 256) {
        int row = i >> 5, c4 = (i & 31) * 4;
        *(float4*)&q_s[row * QROW_PITCH + c4] =
            *(const float4*)(Q + (size_t)(qb * 64 + row) * (NH * HD) + head * HD + c4);
    }

    float4 acc4[8];
#pragma unroll
    for (int c = 0; c < 8; c++) acc4[c] = make_float4(0.f, 0.f, 0.f, 0.f);
    float m_run = -1e30f, l_run = 0.f;

    __syncthreads();

    for (int kt = 0; kt <= qb; kt++) {
        for (int i = tid; i < 64 * 32; i += 256) {
            int row = i >> 5, c4 = (i & 31) * 4;
            size_t base = (size_t)(kt * 64 + row) * (NH * HD) + head * HD + c4;
            *(float4*)&k_s[row * QROW_PITCH + c4] = *(const float4*)(K + base);
            *(float4*)&v_s[row * QROW_PITCH + c4] = *(const float4*)(Vv + base);
        }
        __syncthreads();

        float sc[16];
        const float4* q4 = (const float4*)&q_s[r * QROW_PITCH];
#pragma unroll 2
        for (int jj = 0; jj < 16; jj++) {
            const float4* k4 = (const float4*)&k_s[(g + 4 * jj) * QROW_PITCH];
            float s = 0.f;
#pragma unroll
            for (int d = 0; d < 32; d++) {
                float4 a = q4[d], b = k4[d];
                s += a.x * b.x + a.y * b.y + a.z * b.z + a.w * b.w;
            }
            sc[jj] = s;
        }
        if (kt == qb) {
            int qg = qb * 64 + r;
#pragma unroll
            for (int jj = 0; jj < 16; jj++)
                if (kt * 64 + g + 4 * jj > qg) sc[jj] = -1e30f;
        }

        float mt = sc[0];
#pragma unroll
        for (int jj = 1; jj < 16; jj++) mt = fmaxf(mt, sc[jj]);
        mt = fmaxf(mt, __shfl_xor_sync(0xffffffffu, mt, 1));
        mt = fmaxf(mt, __shfl_xor_sync(0xffffffffu, mt, 2));
        float m_new = fmaxf(m_run, mt);
        float corr  = __expf(m_run - m_new);

        float ps = 0.f;
#pragma unroll
        for (int jj = 0; jj < 16; jj++) {
            float p = __expf(sc[jj] - m_new);
            ps += p;
            p_s[r * P_PITCH + g + 4 * jj] = p;
        }
        ps += __shfl_xor_sync(0xffffffffu, ps, 1);
        ps += __shfl_xor_sync(0xffffffffu, ps, 2);
        l_run = l_run * corr + ps;
        m_run = m_new;
#pragma unroll
        for (int c = 0; c < 8; c++) {
            acc4[c].x *= corr; acc4[c].y *= corr;
            acc4[c].z *= corr; acc4[c].w *= corr;
        }
        __syncthreads();

#pragma unroll 1
        for (int j = 0; j < 64; j++) {
            float p = p_s[r * P_PITCH + j];
            const float* vr = &v_s[j * QROW_PITCH + g * 4];
#pragma unroll
            for (int c = 0; c < 8; c++) {
                float4 v = *(const float4*)(vr + c * 16);
                acc4[c].x += p * v.x; acc4[c].y += p * v.y;
                acc4[c].z += p * v.z; acc4[c].w += p * v.w;
            }
        }
        __syncthreads();
    }

    float inv = 1.f / l_run;
#pragma unroll
    for (int c = 0; c < 8; c++) {
        float4 o;
        o.x = acc4[c].x * inv; o.y = acc4[c].y * inv;
        o.z = acc4[c].z * inv; o.w = acc4[c].w * inv;
        *(float4*)(O + (size_t)(qb * 64 + r) * (NH * HD) + head * HD + g * 4 + c * 16) = o;
    }
}

// ---------------------------------------------------------------------------
extern "C" void kernel_launch(void* const* d_in, const int* in_sizes, int n_in,
                              void* d_out, int out_size) {
    const int*   x   = (const int*)d_in[0];
    const float* emb = (const float*)d_in[1];
    const float* ffw = (const float*)d_in[2];
    const float* qw  = (const float*)d_in[3];
    const float* kw  = (const float*)d_in[4];
    const float* vw  = (const float*)d_in[5];
    const float* ow  = (const float*)d_in[6];
    float* out = (float*)d_out;

    float *h, *hf, *q, *k, *v, *o;
    cudaGetSymbolAddress((void**)&h,  g_h);
    cudaGetSymbolAddress((void**)&hf, g_hf);
    cudaGetSymbolAddress((void**)&q,  g_q);
    cudaGetSymbolAddress((void**)&k,  g_k);
    cudaGetSymbolAddress((void**)&v,  g_v);
    cudaGetSymbolAddress((void**)&o,  g_o);

    const int smemN  = GSTAGES * (ASTG + 16 * BPITCH_N) * 4;   // BT=false
    const int smemT  = GSTAGES * (ASTG + 128 * APITCH) * 4;    // BT=true

    cudaFuncSetAttribute(attn_kernel,
                         cudaFuncAttributeMaxDynamicSharedMemorySize, ATTN_SMEM);
    cudaFuncSetAttribute(gemm3t_kernel<true, false>,
                         cudaFuncAttributeMaxDynamicSharedMemorySize, smemN);
    cudaFuncSetAttribute(gemm3t_kernel<false, false>,
                         cudaFuncAttributeMaxDynamicSharedMemorySize, smemN);
    cudaFuncSetAttribute(gemm3t_kernel<false, true>,
                         cudaFuncAttributeMaxDynamicSharedMemorySize, smemT);
    cudaFuncSetAttribute(gemm3t_qkv_kernel,
                         cudaFuncAttributeMaxDynamicSharedMemorySize, smemN);

    embed_kernel<<<SQ, 256>>>(x, emb, h);

    for (int i = 0; i < NL; i++) {
        const float* ffw_i = ffw + (size_t)i * EDIM * FDIM;
        const float* qw_i  = qw  + (size_t)i * FDIM * NH * HD;
        const float* kw_i  = kw  + (size_t)i * FDIM * NH * HD;
        const float* vw_i  = vw  + (size_t)i * FDIM * NH * HD;
        const float* ow_i  = ow  + (size_t)i * NH * HD * EDIM;

        gemm3t_kernel<true, false><<<dim3(FDIM / 128, SQ / 128), 256, smemN>>>(
            h, ffw_i, hf, SQ, FDIM, EDIM);

        gemm3t_qkv_kernel<<<dim3(NH * HD / 128, SQ / 128, 3), 256, smemN>>>(
            hf, qw_i, kw_i, vw_i, q, k, v, SQ, NH * HD, FDIM);

        attn_kernel<<<dim3(SQ / 64, NH), 256, ATTN_SMEM>>>(q, k, v, o);

        gemm3t_kernel<false, false><<<dim3(EDIM / 128, SQ / 128), 256, smemN>>>(
            o, ow_i, h, SQ, EDIM, NH * HD);
    }

    gemm3t_kernel<false, true><<<dim3(VOC / 128, SQ / 128), 256, smemT>>>(
        h, emb, out, SQ, VOC, EDIM);
}

// round 6
// speedup vs baseline: 5.7835x; 2.1934x over previous
#include <cuda_runtime.h>
#include <cuda_fp16.h>
#include <cstdint>

#define SQ   2048
#define EDIM 1024
#define FDIM 4096
#define NH   8
#define HD   128
#define NL   4
#define VOC  32000
#define HDW  (NH * HD)     // 1024

typedef __half hf;

// ---------------------------------------------------------------------------
// static scratch: fp16 hi/lo planes
// ---------------------------------------------------------------------------
__device__ hf g_hh [SQ * EDIM];
__device__ hf g_hl [SQ * EDIM];
__device__ hf g_hfh[SQ * FDIM];
__device__ hf g_hfl[SQ * FDIM];
__device__ hf g_qh [SQ * HDW];
__device__ hf g_ql [SQ * HDW];
__device__ hf g_kh [SQ * HDW];
__device__ hf g_kl [SQ * HDW];
__device__ hf g_vh [SQ * HDW];
__device__ hf g_vl [SQ * HDW];
__device__ hf g_oh [SQ * HDW];
__device__ hf g_ol [SQ * HDW];
__device__ hf g_ffth[FDIM * EDIM];
__device__ hf g_fftl[FDIM * EDIM];
__device__ hf g_qth [HDW * FDIM];
__device__ hf g_qtl [HDW * FDIM];
__device__ hf g_kth [HDW * FDIM];
__device__ hf g_ktl [HDW * FDIM];
__device__ hf g_vth [HDW * FDIM];
__device__ hf g_vtl [HDW * FDIM];
__device__ hf g_oth [EDIM * HDW];
__device__ hf g_otl [EDIM * HDW];
__device__ hf g_eth [VOC * EDIM];
__device__ hf g_etl [VOC * EDIM];

// ---------------------------------------------------------------------------
// helpers
// ---------------------------------------------------------------------------
__device__ __forceinline__ uint32_t smem_u32(const void* p) {
    return (uint32_t)__cvta_generic_to_shared(p);
}
__device__ __forceinline__ void cp_async16(uint32_t dst, const void* src) {
    asm volatile("cp.async.cg.shared.global [%0], [%1], 16;\n" :: "r"(dst), "l"(src));
}
__device__ __forceinline__ void cp_commit() {
    asm volatile("cp.async.commit_group;\n");
}
template <int N>
__device__ __forceinline__ void cp_wait() {
    asm volatile("cp.async.wait_group %0;\n" :: "n"(N));
}
__device__ __forceinline__ void mma16(float* c, const uint32_t* a, uint32_t b0, uint32_t b1) {
    asm volatile(
        "mma.sync.aligned.m16n8k16.row.col.f32.f16.f16.f32 "
        "{%0,%1,%2,%3}, {%4,%5,%6,%7}, {%8,%9}, {%0,%1,%2,%3};\n"
        : "+f"(c[0]), "+f"(c[1]), "+f"(c[2]), "+f"(c[3])
        : "r"(a[0]), "r"(a[1]), "r"(a[2]), "r"(a[3]), "r"(b0), "r"(b1));
}
__device__ __forceinline__ void ldsm4(uint32_t* r, uint32_t a) {
    asm volatile("ldmatrix.sync.aligned.m8n8.x4.shared.b16 {%0,%1,%2,%3}, [%4];"
                 : "=r"(r[0]), "=r"(r[1]), "=r"(r[2]), "=r"(r[3]) : "r"(a));
}
__device__ __forceinline__ void ldsm4t(uint32_t* r, uint32_t a) {
    asm volatile("ldmatrix.sync.aligned.m8n8.x4.trans.shared.b16 {%0,%1,%2,%3}, [%4];"
                 : "=r"(r[0]), "=r"(r[1]), "=r"(r[2]), "=r"(r[3]) : "r"(a));
}
__device__ __forceinline__ uint32_t pk(hf a, hf b) {
    return ((uint32_t)__half_as_ushort(b) << 16) | __half_as_ushort(a);
}
__device__ __forceinline__ void split2(float f0, float f1, uint32_t& h, uint32_t& l) {
    hf h0 = __float2half_rn(f0), h1 = __float2half_rn(f1);
    hf l0 = __float2half_rn(f0 - __half2float(h0));
    hf l1 = __float2half_rn(f1 - __half2float(h1));
    h = pk(h0, h1);
    l = pk(l0, l1);
}

// ---------------------------------------------------------------------------
// fp16 3-term GEMM: C[M,N] = op(A @ B^T); A[M,K], B[N,K] hi/lo half planes.
// CTA 128x128, BK=32, 8 warps (2x4), warp tile 64x32, 3-stage cp.async.
// smem rows: 32 halfs (64B) at 80B pitch (conflict-free ldmatrix + stores).
// ---------------------------------------------------------------------------
#define GPL   10240                // 128 * 80 bytes per plane
#define GSTG  (4 * GPL)            // Ah, Al, Bh, Bl
#define GSMEM (3 * GSTG)           // 122880

template <int RELU, int SPLIT>
__device__ __forceinline__ void hgemm_body(
    const hf* __restrict__ Ah_, const hf* __restrict__ Al_,
    const hf* __restrict__ Bh_, const hf* __restrict__ Bl_,
    float* __restrict__ C, hf* __restrict__ Ch, hf* __restrict__ Cl,
    int M, int N, int K, int m0, int n0)
{
    extern __shared__ char smraw[];
    uint32_t sb = smem_u32(smraw);
    const int tid = threadIdx.x, lane = tid & 31, warp = tid >> 5;
    const int wr = warp >> 2, wc = warp & 3;
    const int lq = lane >> 2, lr = lane & 3;

    const hf* src[4] = { Ah_ + (size_t)m0 * K, Al_ + (size_t)m0 * K,
                         Bh_ + (size_t)n0 * K, Bl_ + (size_t)n0 * K };
    // per-thread cp.async coords: 2 chunks per plane
    const int crow = tid >> 2, cc = tid & 3;           // chunk row / 16B col

    auto issue = [&](int st, int k0) {
        uint32_t base = sb + (uint32_t)st * GSTG;
#pragma unroll
        for (int pl = 0; pl < 4; pl++) {
#pragma unroll
            for (int u = 0; u < 2; u++) {
                int row = crow + u * 64;
                cp_async16(base + pl * GPL + row * 80 + cc * 16,
                           src[pl] + (size_t)row * K + k0 + cc * 8);
            }
        }
        cp_commit();
    };

    // fragment lane offsets
    const uint32_t a_off = (uint32_t)(wr * 64 + (lane & 15)) * 80 +
                           (uint32_t)(((lane >> 4) & 1) * 8) * 2;
    const uint32_t b_off = (uint32_t)(wc * 32 + ((lane >> 4) & 1) * 8 + (lane & 7)) * 80 +
                           (uint32_t)(((lane >> 3) & 1) * 8) * 2;

    float acc[4][4][4];
#pragma unroll
    for (int i = 0; i < 4; i++)
#pragma unroll
        for (int j = 0; j < 4; j++)
#pragma unroll
            for (int q = 0; q < 4; q++) acc[i][j][q] = 0.f;

    const int KT = K >> 5;
    issue(0, 0);
    issue(1, 32);

    for (int kt = 0; kt < KT; kt++) {
        if (kt + 1 < KT) cp_wait<1>(); else cp_wait<0>();
        __syncthreads();
        if (kt + 2 < KT) issue((kt + 2) % 3, (kt + 2) * 32);
        else cp_commit();

        uint32_t stg = sb + (uint32_t)(kt % 3) * GSTG;
#pragma unroll
        for (int ks = 0; ks < 2; ks++) {
            uint32_t ah[4][4], al[4][4];
#pragma unroll
            for (int mt = 0; mt < 4; mt++) {
                uint32_t ad = stg + a_off + mt * (16 * 80) + ks * 32;
                ldsm4(ah[mt], ad);
                ldsm4(al[mt], ad + GPL);
            }
            uint32_t bh[2][4], bl[2][4];
#pragma unroll
            for (int pr = 0; pr < 2; pr++) {
                uint32_t bd = stg + 2 * GPL + b_off + pr * (16 * 80) + ks * 32;
                ldsm4(bh[pr], bd);
                ldsm4(bl[pr], bd + GPL);
            }
#pragma unroll
            for (int mt = 0; mt < 4; mt++)
#pragma unroll
                for (int pr = 0; pr < 2; pr++)
#pragma unroll
                    for (int oc = 0; oc < 2; oc++) {
                        int nt = pr * 2 + oc;
                        mma16(acc[mt][nt], ah[mt], bh[pr][2*oc], bh[pr][2*oc+1]);
                        mma16(acc[mt][nt], ah[mt], bl[pr][2*oc], bl[pr][2*oc+1]);
                        mma16(acc[mt][nt], al[mt], bh[pr][2*oc], bh[pr][2*oc+1]);
                    }
        }
    }

    // epilogue
#pragma unroll
    for (int mt = 0; mt < 4; mt++) {
        int r0 = m0 + wr * 64 + mt * 16 + lq;
#pragma unroll
        for (int nt = 0; nt < 4; nt++) {
            int col = n0 + wc * 32 + nt * 8 + lr * 2;
            float v0 = acc[mt][nt][0], v1 = acc[mt][nt][1];
            float v2 = acc[mt][nt][2], v3 = acc[mt][nt][3];
            if (RELU) {
                v0 = fmaxf(v0, 0.f); v1 = fmaxf(v1, 0.f);
                v2 = fmaxf(v2, 0.f); v3 = fmaxf(v3, 0.f);
            }
            if (SPLIT == 0) {
                *(float2*)(C + (size_t)r0 * N + col) = make_float2(v0, v1);
                *(float2*)(C + (size_t)(r0 + 8) * N + col) = make_float2(v2, v3);
            } else {
                uint32_t h, l;
                split2(v0, v1, h, l);
                *(uint32_t*)(Ch + (size_t)r0 * N + col) = h;
                *(uint32_t*)(Cl + (size_t)r0 * N + col) = l;
                split2(v2, v3, h, l);
                *(uint32_t*)(Ch + (size_t)(r0 + 8) * N + col) = h;
                *(uint32_t*)(Cl + (size_t)(r0 + 8) * N + col) = l;
            }
        }
    }
}

template <int RELU, int SPLIT>
__global__ __launch_bounds__(256)
void hgemm_kernel(const hf* __restrict__ Ah, const hf* __restrict__ Al,
                  const hf* __restrict__ Bh, const hf* __restrict__ Bl,
                  float* __restrict__ C, hf* __restrict__ Ch, hf* __restrict__ Cl,
                  int M, int N, int K) {
    hgemm_body<RELU, SPLIT>(Ah, Al, Bh, Bl, C, Ch, Cl, M, N, K,
                            blockIdx.y * 128, blockIdx.x * 128);
}

__global__ __launch_bounds__(256)
void hgemm_qkv(const hf* __restrict__ Ah, const hf* __restrict__ Al,
               const hf* __restrict__ B0h, const hf* __restrict__ B0l,
               const hf* __restrict__ B1h, const hf* __restrict__ B1l,
               const hf* __restrict__ B2h, const hf* __restrict__ B2l,
               hf* __restrict__ C0h, hf* __restrict__ C0l,
               hf* __restrict__ C1h, hf* __restrict__ C1l,
               hf* __restrict__ C2h, hf* __restrict__ C2l,
               int M, int N, int K) {
    const hf* Bh = (blockIdx.z == 0) ? B0h : (blockIdx.z == 1) ? B1h : B2h;
    const hf* Bl = (blockIdx.z == 0) ? B0l : (blockIdx.z == 1) ? B1l : B2l;
    hf* Ch = (blockIdx.z == 0) ? C0h : (blockIdx.z == 1) ? C1h : C2h;
    hf* Cl = (blockIdx.z == 0) ? C0l : (blockIdx.z == 1) ? C1l : C2l;
    hgemm_body<0, 1>(Ah, Al, Bh, Bl, nullptr, Ch, Cl, M, N, K,
                     blockIdx.y * 128, blockIdx.x * 128);
}

// ---------------------------------------------------------------------------
// weight transpose + fp16 hi/lo split: W[R,C] fp32 -> Th,Tl[C,R] half
// ---------------------------------------------------------------------------
__global__ __launch_bounds__(256)
void wconv_t(const float* __restrict__ W, hf* __restrict__ Th,
             hf* __restrict__ Tl, int R, int Cc) {
    __shared__ float t[32][33];
    int c0 = blockIdx.x * 32, r0 = blockIdx.y * 32;
    int tx = threadIdx.x & 31, ty = threadIdx.x >> 5;
#pragma unroll
    for (int i = 0; i < 32; i += 8)
        t[ty + i][tx] = W[(size_t)(r0 + ty + i) * Cc + c0 + tx];
    __syncthreads();
#pragma unroll
    for (int i = 0; i < 32; i += 8) {
        float v = t[tx][ty + i];
        hf h = __float2half_rn(v);
        hf l = __float2half_rn(v - __half2float(h));
        size_t o = (size_t)(c0 + ty + i) * R + r0 + tx;
        Th[o] = h;
        Tl[o] = l;
    }
}

// straight split (for embedding matrix as logits B; already [N,K])
__global__ __launch_bounds__(256)
void conv_split(const float* __restrict__ X, hf* __restrict__ Xh,
                hf* __restrict__ Xl, int n4) {
    int i = blockIdx.x * 256 + threadIdx.x;
    if (i >= n4) return;
    float4 v = ((const float4*)X)[i];
    uint32_t h0, l0, h1, l1;
    split2(v.x, v.y, h0, l0);
    split2(v.z, v.w, h1, l1);
    ((uint2*)Xh)[i] = make_uint2(h0, h1);
    ((uint2*)Xl)[i] = make_uint2(l0, l1);
}

__global__ void embed_kernel(const int* __restrict__ x,
                             const float* __restrict__ emb,
                             hf* __restrict__ hh, hf* __restrict__ hl) {
    int s = blockIdx.x;
    int tok = x[s];
    const float4* src = (const float4*)(emb + (size_t)tok * EDIM);
    uint2* dh = (uint2*)(hh + (size_t)s * EDIM);
    uint2* dl = (uint2*)(hl + (size_t)s * EDIM);
    for (int i = threadIdx.x; i < EDIM / 4; i += blockDim.x) {
        float4 v = src[i];
        uint32_t h0, l0, h1, l1;
        split2(v.x, v.y, h0, l0);
        split2(v.z, v.w, h1, l1);
        dh[i] = make_uint2(h0, h1);
        dl[i] = make_uint2(l0, l1);
    }
}

// ---------------------------------------------------------------------------
// Flash attention with fp16 mma, 3-term splits for QK and PV.
// CTA: 128 queries x 1 head; 8 warps x 16 rows. Key tiles of 64, 3-stage.
// Q frags live in registers; P exp'd/split/packed in registers.
// smem row pitch 272B (conflict-free ldmatrix: bank base 4*row mod 32).
// ---------------------------------------------------------------------------
#define KP    272                    // bytes per 128-half row
#define APL   (64 * KP)              // 17408 per plane
#define ASTG4 (4 * APL)              // Kh,Kl,Vh,Vl per stage
#define ATT_SMEM (3 * ASTG4)         // 208896

__global__ __launch_bounds__(256)
void attn_mma(const hf* __restrict__ Qh, const hf* __restrict__ Ql,
              const hf* __restrict__ Kh, const hf* __restrict__ Kl,
              const hf* __restrict__ Vh, const hf* __restrict__ Vl,
              hf* __restrict__ Oh, hf* __restrict__ Ol) {
    extern __shared__ char smraw[];
    uint32_t sb = smem_u32(smraw);
    const int tid = threadIdx.x, lane = tid & 31, warp = tid >> 5;
    const int lq = lane >> 2, lr = lane & 3;
    const int qb = blockIdx.x, head = blockIdx.y;

    // ---- stage Q through smem (uses stage-0 area), build register frags ----
    {
        const hf* qsrc[2] = { Qh, Ql };
#pragma unroll
        for (int pl = 0; pl < 2; pl++)
#pragma unroll
            for (int u = 0; u < 8; u++) {
                int id = tid + u * 256;
                int row = id >> 4, c = id & 15;
                cp_async16(sb + pl * (2 * APL) + row * KP + c * 16,
                           qsrc[pl] + (size_t)(qb * 128 + row) * HDW + head * HD + c * 8);
            }
        cp_commit();
        cp_wait<0>();
        __syncthreads();
    }
    uint32_t qfh[8][4], qfl[8][4];
    {
        uint32_t q_off = (uint32_t)(warp * 16 + (lane & 15)) * KP +
                         (uint32_t)(((lane >> 4) & 1) * 8) * 2;
#pragma unroll
        for (int kc = 0; kc < 8; kc++) {
            ldsm4(qfh[kc], sb + q_off + kc * 32);
            ldsm4(qfl[kc], sb + 2 * APL + q_off + kc * 32);
        }
    }
    __syncthreads();

    const hf* kvsrc[4] = { Kh, Kl, Vh, Vl };
    auto loadKV = [&](int t, int st) {
        uint32_t base = sb + (uint32_t)st * ASTG4;
#pragma unroll
        for (int pl = 0; pl < 4; pl++)
#pragma unroll
            for (int u = 0; u < 4; u++) {
                int id = tid + u * 256;
                int row = id >> 4, c = id & 15;
                cp_async16(base + pl * APL + row * KP + c * 16,
                           kvsrc[pl] + (size_t)(t * 64 + row) * HDW + head * HD + c * 8);
            }
        cp_commit();
    };

    float o_acc[16][4];
#pragma unroll
    for (int i = 0; i < 16; i++)
#pragma unroll
        for (int j = 0; j < 4; j++) o_acc[i][j] = 0.f;
    float mrun[2] = { -1e30f, -1e30f };
    float lrun[2] = { 0.f, 0.f };

    const int NT = 2 * qb + 2;
    loadKV(0, 0);
    if (NT > 1) loadKV(1, 1);

    const uint32_t k_off = (uint32_t)(((lane >> 4) & 1) * 8 + (lane & 7)) * KP +
                           (uint32_t)(((lane >> 3) & 1) * 8) * 2;
    const uint32_t v_off = (uint32_t)(((lane >> 3) & 1) * 8 + (lane & 7)) * KP +
                           (uint32_t)(((lane >> 4) & 1) * 8) * 2;

    for (int t = 0; t < NT; t++) {
        if (t + 1 < NT) cp_wait<1>(); else cp_wait<0>();
        __syncthreads();
        if (t + 2 < NT) loadKV(t + 2, (t + 2) % 3);
        else cp_commit();

        uint32_t stg = sb + (uint32_t)(t % 3) * ASTG4;

        // ---- S = Q K^T (3-term) ----
        float s_acc[8][4];
#pragma unroll
        for (int i = 0; i < 8; i++)
#pragma unroll
            for (int j = 0; j < 4; j++) s_acc[i][j] = 0.f;

#pragma unroll
        for (int kc = 0; kc < 8; kc++) {
            uint32_t kbh[4][4], kbl[4][4];
#pragma unroll
            for (int pr = 0; pr < 4; pr++) {
                uint32_t ad = stg + k_off + pr * (16 * KP) + kc * 32;
                ldsm4(kbh[pr], ad);
                ldsm4(kbl[pr], ad + APL);
            }
#pragma unroll
            for (int pr = 0; pr < 4; pr++)
#pragma unroll
                for (int oc = 0; oc < 2; oc++) {
                    int nt = pr * 2 + oc;
                    mma16(s_acc[nt], qfh[kc], kbh[pr][2*oc], kbh[pr][2*oc+1]);
                    mma16(s_acc[nt], qfh[kc], kbl[pr][2*oc], kbl[pr][2*oc+1]);
                    mma16(s_acc[nt], qfl[kc], kbh[pr][2*oc], kbh[pr][2*oc+1]);
                }
        }

        // ---- causal mask (diagonal region only) ----
        if (t >= 2 * qb) {
            int rbase = qb * 128 + warp * 16 + lq;
#pragma unroll
            for (int nt = 0; nt < 8; nt++)
#pragma unroll
                for (int rr = 0; rr < 4; rr++) {
                    int col = t * 64 + nt * 8 + 2 * lr + (rr & 1);
                    int row = rbase + (rr >> 1) * 8;
                    if (col > row) s_acc[nt][rr] = -1e30f;
                }
        }

        // ---- online softmax ----
#pragma unroll
        for (int h = 0; h < 2; h++) {
            float mloc = -1e30f;
#pragma unroll
            for (int nt = 0; nt < 8; nt++) {
                mloc = fmaxf(mloc, s_acc[nt][2*h]);
                mloc = fmaxf(mloc, s_acc[nt][2*h+1]);
            }
            mloc = fmaxf(mloc, __shfl_xor_sync(0xffffffffu, mloc, 1));
            mloc = fmaxf(mloc, __shfl_xor_sync(0xffffffffu, mloc, 2));
            float mnew = fmaxf(mrun[h], mloc);
            float corr = __expf(mrun[h] - mnew);
            mrun[h] = mnew;
            float ps = 0.f;
#pragma unroll
            for (int nt = 0; nt < 8; nt++) {
                float p0 = __expf(s_acc[nt][2*h]   - mnew);
                float p1 = __expf(s_acc[nt][2*h+1] - mnew);
                s_acc[nt][2*h] = p0;
                s_acc[nt][2*h+1] = p1;
                ps += p0 + p1;
            }
            ps += __shfl_xor_sync(0xffffffffu, ps, 1);
            ps += __shfl_xor_sync(0xffffffffu, ps, 2);
            lrun[h] = lrun[h] * corr + ps;
#pragma unroll
            for (int nt = 0; nt < 16; nt++) {
                o_acc[nt][2*h]   *= corr;
                o_acc[nt][2*h+1] *= corr;
            }
        }

        // ---- O += P V (3-term) ----
#pragma unroll
        for (int kc2 = 0; kc2 < 4; kc2++) {
            uint32_t ph[4], pl[4];
            split2(s_acc[2*kc2][0],   s_acc[2*kc2][1],   ph[0], pl[0]);
            split2(s_acc[2*kc2][2],   s_acc[2*kc2][3],   ph[1], pl[1]);
            split2(s_acc[2*kc2+1][0], s_acc[2*kc2+1][1], ph[2], pl[2]);
            split2(s_acc[2*kc2+1][2], s_acc[2*kc2+1][3], ph[3], pl[3]);
#pragma unroll
            for (int dp = 0; dp < 8; dp++) {
                uint32_t vbh[4], vbl[4];
                uint32_t ad = stg + 2 * APL + v_off + kc2 * (16 * KP) + dp * 32;
                ldsm4t(vbh, ad);
                ldsm4t(vbl, ad + APL);
#pragma unroll
                for (int oc = 0; oc < 2; oc++) {
                    int nt = dp * 2 + oc;
                    mma16(o_acc[nt], ph, vbh[2*oc], vbh[2*oc+1]);
                    mma16(o_acc[nt], ph, vbl[2*oc], vbl[2*oc+1]);
                    mma16(o_acc[nt], pl, vbh[2*oc], vbh[2*oc+1]);
                }
            }
        }
    }

    // ---- epilogue: normalize, split to hi/lo planes ----
    float inv0 = 1.f / lrun[0], inv1 = 1.f / lrun[1];
    int r0 = qb * 128 + warp * 16 + lq;
#pragma unroll
    for (int nt = 0; nt < 16; nt++) {
        int col = head * HD + nt * 8 + 2 * lr;
        uint32_t h, l;
        split2(o_acc[nt][0] * inv0, o_acc[nt][1] * inv0, h, l);
        *(uint32_t*)(Oh + (size_t)r0 * HDW + col) = h;
        *(uint32_t*)(Ol + (size_t)r0 * HDW + col) = l;
        split2(o_acc[nt][2] * inv1, o_acc[nt][3] * inv1, h, l);
        *(uint32_t*)(Oh + (size_t)(r0 + 8) * HDW + col) = h;
        *(uint32_t*)(Ol + (size_t)(r0 + 8) * HDW + col) = l;
    }
}

// ---------------------------------------------------------------------------
extern "C" void kernel_launch(void* const* d_in, const int* in_sizes, int n_in,
                              void* d_out, int out_size) {
    const int*   x   = (const int*)d_in[0];
    const float* emb = (const float*)d_in[1];
    const float* ffw = (const float*)d_in[2];   // [L,E,F]
    const float* qw  = (const float*)d_in[3];   // [L,F,H*D]
    const float* kw  = (const float*)d_in[4];
    const float* vw  = (const float*)d_in[5];
    const float* ow  = (const float*)d_in[6];   // [L,H*D,E]
    float* out = (float*)d_out;

    hf *hh, *hl, *hfh, *hfl, *qh, *ql, *kh, *kl, *vh, *vl, *oh, *ol;
    hf *ffth, *fftl, *qth, *qtl, *kth, *ktl, *vth, *vtl, *oth, *otl, *eth, *etl;
    cudaGetSymbolAddress((void**)&hh,  g_hh);  cudaGetSymbolAddress((void**)&hl,  g_hl);
    cudaGetSymbolAddress((void**)&hfh, g_hfh); cudaGetSymbolAddress((void**)&hfl, g_hfl);
    cudaGetSymbolAddress((void**)&qh,  g_qh);  cudaGetSymbolAddress((void**)&ql,  g_ql);
    cudaGetSymbolAddress((void**)&kh,  g_kh);  cudaGetSymbolAddress((void**)&kl,  g_kl);
    cudaGetSymbolAddress((void**)&vh,  g_vh);  cudaGetSymbolAddress((void**)&vl,  g_vl);
    cudaGetSymbolAddress((void**)&oh,  g_oh);  cudaGetSymbolAddress((void**)&ol,  g_ol);
    cudaGetSymbolAddress((void**)&ffth, g_ffth); cudaGetSymbolAddress((void**)&fftl, g_fftl);
    cudaGetSymbolAddress((void**)&qth,  g_qth);  cudaGetSymbolAddress((void**)&qtl,  g_qtl);
    cudaGetSymbolAddress((void**)&kth,  g_kth);  cudaGetSymbolAddress((void**)&ktl,  g_ktl);
    cudaGetSymbolAddress((void**)&vth,  g_vth);  cudaGetSymbolAddress((void**)&vtl,  g_vtl);
    cudaGetSymbolAddress((void**)&oth,  g_oth);  cudaGetSymbolAddress((void**)&otl,  g_otl);
    cudaGetSymbolAddress((void**)&eth,  g_eth);  cudaGetSymbolAddress((void**)&etl,  g_etl);

    cudaFuncSetAttribute(attn_mma,
                         cudaFuncAttributeMaxDynamicSharedMemorySize, ATT_SMEM);
    cudaFuncSetAttribute(hgemm_kernel<1, 1>,
                         cudaFuncAttributeMaxDynamicSharedMemorySize, GSMEM);
    cudaFuncSetAttribute(hgemm_kernel<0, 1>,
                         cudaFuncAttributeMaxDynamicSharedMemorySize, GSMEM);
    cudaFuncSetAttribute(hgemm_kernel<0, 0>,
                         cudaFuncAttributeMaxDynamicSharedMemorySize, GSMEM);
    cudaFuncSetAttribute(hgemm_qkv,
                         cudaFuncAttributeMaxDynamicSharedMemorySize, GSMEM);

    embed_kernel<<<SQ, 256>>>(x, emb, hh, hl);
    conv_split<<<(VOC * EDIM / 4 + 255) / 256, 256>>>(emb, eth, etl, VOC * EDIM / 4);

    for (int i = 0; i < NL; i++) {
        const float* ffw_i = ffw + (size_t)i * EDIM * FDIM;
        const float* qw_i  = qw  + (size_t)i * FDIM * HDW;
        const float* kw_i  = kw  + (size_t)i * FDIM * HDW;
        const float* vw_i  = vw  + (size_t)i * FDIM * HDW;
        const float* ow_i  = ow  + (size_t)i * HDW * EDIM;

        wconv_t<<<dim3(FDIM / 32, EDIM / 32), 256>>>(ffw_i, ffth, fftl, EDIM, FDIM);
        wconv_t<<<dim3(HDW / 32, FDIM / 32), 256>>>(qw_i, qth, qtl, FDIM, HDW);
        wconv_t<<<dim3(HDW / 32, FDIM / 32), 256>>>(kw_i, kth, ktl, FDIM, HDW);
        wconv_t<<<dim3(HDW / 32, FDIM / 32), 256>>>(vw_i, vth, vtl, FDIM, HDW);
        wconv_t<<<dim3(EDIM / 32, HDW / 32), 256>>>(ow_i, oth, otl, HDW, EDIM);

        // hf = relu(h @ ff_w): [2048,1024] @ [1024,4096]
        hgemm_kernel<1, 1><<<dim3(FDIM / 128, SQ / 128), 256, GSMEM>>>(
            hh, hl, ffth, fftl, nullptr, hfh, hfl, SQ, FDIM, EDIM);

        // q,k,v = hf @ w: [2048,4096] @ [4096,1024]
        hgemm_qkv<<<dim3(HDW / 128, SQ / 128, 3), 256, GSMEM>>>(
            hfh, hfl, qth, qtl, kth, ktl, vth, vtl,
            qh, ql, kh, kl, vh, vl, SQ, HDW, FDIM);

        // attention
        attn_mma<<<dim3(SQ / 128, NH), 256, ATT_SMEM>>>(
            qh, ql, kh, kl, vh, vl, oh, ol);

        // h = o @ o_w: [2048,1024] @ [1024,1024]
        hgemm_kernel<0, 1><<<dim3(EDIM / 128, SQ / 128), 256, GSMEM>>>(
            oh, ol, oth, otl, nullptr, hh, hl, SQ, EDIM, HDW);
    }

    // logits = h @ emb^T: [2048,1024] @ [32000,1024]^T
    hgemm_kernel<0, 0><<<dim3(VOC / 128, SQ / 128), 256, GSMEM>>>(
        hh, hl, eth, etl, out, nullptr, nullptr, SQ, VOC, EDIM);
}